// round 4
// baseline (speedup 1.0000x reference)
#include <cuda_runtime.h>

// MC_Module_Batch: bilinear backward warp + weight + sum over R, via SMEM tile staging.
// pred [B,R,C,H,W], mv [B,R,2,H,W] (quarter-pel), weight [B,R,1,H,W] -> out [B,C,H,W]
// B=4, R=2, C=19, H=256, W=512

#define Bv 4
#define Rv 2
#define Cv 19
#define Hv 256
#define Wv 512
#define HW (Hv * Wv)

#define PADY 8
#define TROWS (32 + 2 * PADY + 1)   // 49
#define TCOLS 64
#define TSZ (TROWS * TCOLS)         // 3136 floats
#define TSZ4 (TSZ / 4)              // 784 float4

__global__ __launch_bounds__(256, 3)
void mc_warp_kernel(const float* __restrict__ pred,
                    const float* __restrict__ mv,
                    const float* __restrict__ wgt,
                    float* __restrict__ out)
{
    __shared__ __align__(16) float tile[2][TSZ + 4];

    const int tid = threadIdx.x;
    const int tx  = tid & 31;
    const int ty  = tid >> 5;
    const int bx  = blockIdx.x, by = blockIdx.y, b = blockIdx.z;
    const int x0blk = bx * 32;
    const int y0blk = by * 32;
    const int x = x0blk + tx;
    const int colbase = x0blk - 16;     // tile covers cols [colbase, colbase+63]
    const int rowbase = y0blk - PADY;   // tile covers rows [rowbase, rowbase+48]

    // ---- Precompute taps: per output pixel (4 per thread) per r ----
    // Descriptor: bit30 = fallback flag, bit20 = dx (cx1-cx0), low 20 bits = index
    float w4[4][2][4];
    int   ia[4][2];   // top-row tap descriptor
    int   ib[4][2];   // bottom-row index (fast: tile idx | fallback: global idx)
#pragma unroll
    for (int k = 0; k < 4; ++k) {
        const int y = y0blk + ty + 8 * k;
        const int pix = y * Wv + x;
#pragma unroll
        for (int r = 0; r < Rv; ++r) {
            const int nr = b * Rv + r;
            const float mvx = __ldg(mv + (size_t)(nr * 2) * HW + pix) * 0.25f;
            const float mvy = __ldg(mv + (size_t)(nr * 2 + 1) * HW + pix) * 0.25f;
            const float w   = __ldg(wgt + (size_t)nr * HW + pix);

            const float gx = (float)x + mvx;
            const float gy = (float)y + mvy;
            const float x0f = floorf(gx), y0f = floorf(gy);
            const float wx1 = gx - x0f, wx0 = 1.0f - wx1;
            const float wy1 = gy - y0f, wy0 = 1.0f - wy1;

            const int x0 = (int)x0f, y0 = (int)y0f;
            const int x1 = x0 + 1,   y1 = y0 + 1;

            const float vx0 = ((unsigned)x0 < (unsigned)Wv) ? 1.0f : 0.0f;
            const float vx1 = ((unsigned)x1 < (unsigned)Wv) ? 1.0f : 0.0f;
            const float vy0 = ((unsigned)y0 < (unsigned)Hv) ? 1.0f : 0.0f;
            const float vy1 = ((unsigned)y1 < (unsigned)Hv) ? 1.0f : 0.0f;

            const int cx0 = min(max(x0, 0), Wv - 1);
            const int cx1 = min(max(x1, 0), Wv - 1);   // independently clamped!
            const int cy0 = min(max(y0, 0), Hv - 1);
            const int cy1 = min(max(y1, 0), Hv - 1);
            const int dx  = cx1 - cx0;                 // 0 or 1

            w4[k][r][0] = wy0 * wx0 * vy0 * vx0 * w;
            w4[k][r][1] = wy0 * wx1 * vy0 * vx1 * w;
            w4[k][r][2] = wy1 * wx0 * vy1 * vx0 * w;
            w4[k][r][3] = wy1 * wx1 * vy1 * vx1 * w;

            const int tT = cy0 - rowbase;
            const int tB = cy1 - rowbase;
            const int tX = cx0 - colbase;
            if ((unsigned)tT < TROWS && (unsigned)tB < TROWS &&
                (unsigned)tX <= (TCOLS - 2)) {
                ia[k][r] = (dx << 20) | (tT * TCOLS + tX);
                ib[k][r] = tB * TCOLS + tX;
            } else {
                ia[k][r] = 0x40000000 | (dx << 20) | (cy0 * Wv + cx0);
                ib[k][r] = cy1 * Wv + cx0;
            }
        }
    }

    const float* pbase0 = pred + (size_t)(b * Rv + 0) * Cv * HW;
    const float* pbase1 = pred + (size_t)(b * Rv + 1) * Cv * HW;
    const bool edge = (bx == 0) || (bx == (Wv / 32 - 1));

    float* ob = out + (size_t)b * Cv * HW + (size_t)(y0blk + ty) * Wv + x;

    for (int c = 0; c < Cv; ++c) {
        __syncthreads();   // previous iteration's gathers done before overwrite
        // ---- cooperative tile load for both r ----
        if (!edge) {
            const float4* s0 = (const float4*)(pbase0 + (size_t)c * HW);
            const float4* s1 = (const float4*)(pbase1 + (size_t)c * HW);
            float4* t0 = (float4*)tile[0];
            float4* t1 = (float4*)tile[1];
            const int cb4 = colbase >> 2;
#pragma unroll
            for (int i = tid; i < TSZ4; i += 256) {
                const int row = i >> 4;          // 16 float4 per tile row
                const int c4  = i & 15;
                const int gcy = min(max(rowbase + row, 0), Hv - 1);
                const int gi  = gcy * (Wv / 4) + cb4 + c4;
                t0[i] = s0[gi];
                t1[i] = s1[gi];
            }
        } else {
            const float* s0 = pbase0 + (size_t)c * HW;
            const float* s1 = pbase1 + (size_t)c * HW;
#pragma unroll 4
            for (int i = tid; i < TSZ; i += 256) {
                const int row = i >> 6;
                const int col = i & 63;
                const int gcy = min(max(rowbase + row, 0), Hv - 1);
                const int gcx = min(max(colbase + col, 0), Wv - 1);
                const int gi  = gcy * Wv + gcx;
                tile[0][i] = __ldg(s0 + gi);
                tile[1][i] = __ldg(s1 + gi);
            }
        }
        __syncthreads();

        // ---- gather + accumulate ----
        float acc[4];
#pragma unroll
        for (int k = 0; k < 4; ++k) {
            float s = 0.0f;
#pragma unroll
            for (int r = 0; r < Rv; ++r) {
                const int A  = ia[k][r];
                const int Bi = ib[k][r];
                const int dx = (A >> 20) & 1;
                const int iT = A & 0xFFFFF;
                float t0v, t1v, b0v, b1v;
                if (A < 0x40000000) {
                    t0v = tile[r][iT];
                    t1v = tile[r][iT + dx];
                    b0v = tile[r][Bi];
                    b1v = tile[r][Bi + dx];
                } else {
                    const float* pc = (r ? pbase1 : pbase0) + (size_t)c * HW;
                    t0v = __ldg(pc + iT);
                    t1v = __ldg(pc + iT + dx);
                    b0v = __ldg(pc + Bi);
                    b1v = __ldg(pc + Bi + dx);
                }
                s = fmaf(w4[k][r][0], t0v,
                    fmaf(w4[k][r][1], t1v,
                    fmaf(w4[k][r][2], b0v,
                    fmaf(w4[k][r][3], b1v, s))));
            }
            acc[k] = s;
        }

        // ---- coalesced store ----
        float* oc = ob + (size_t)c * HW;
#pragma unroll
        for (int k = 0; k < 4; ++k) {
            oc[(size_t)(8 * k) * Wv] = acc[k];
        }
    }
}

extern "C" void kernel_launch(void* const* d_in, const int* in_sizes, int n_in,
                              void* d_out, int out_size)
{
    const float* pred = (const float*)d_in[0];
    const float* mv   = (const float*)d_in[1];
    const float* wgt  = (const float*)d_in[2];
    float* out        = (float*)d_out;

    dim3 grid(Wv / 32, Hv / 32, Bv);   // 16 x 8 x 4 = 512 blocks
    mc_warp_kernel<<<grid, 256>>>(pred, mv, wgt, out);
}

// round 5
// speedup vs baseline: 1.5839x; 1.5839x over previous
#include <cuda_runtime.h>
#include <cstdint>

// MC_Module_Batch: bilinear backward warp + weight + sum over R.
// SMEM tile staging with 2-stage cp.async pipeline over channels.
// pred [B,R,C,H,W], mv [B,R,2,H,W] (quarter-pel), weight [B,R,1,H,W] -> out [B,C,H,W]

#define Bv 4
#define Rv 2
#define Cv 19
#define Hv 256
#define Wv 512
#define HW (Hv * Wv)

#define PADY 6
#define TROWS (32 + 2 * PADY + 1)   // 45
#define TCOLS 64
#define TSZ (TROWS * TCOLS)         // 2880 floats (11.25 KB)
#define TSZ4 (TSZ / 4)              // 720 float4

__device__ __forceinline__ void cp_async16(uint32_t smem, const void* g) {
    asm volatile("cp.async.cg.shared.global [%0], [%1], 16;" :: "r"(smem), "l"(g));
}
__device__ __forceinline__ void cp_async4(uint32_t smem, const void* g) {
    asm volatile("cp.async.ca.shared.global [%0], [%1], 4;" :: "r"(smem), "l"(g));
}
__device__ __forceinline__ void cp_commit() {
    asm volatile("cp.async.commit_group;");
}
template<int N> __device__ __forceinline__ void cp_wait() {
    asm volatile("cp.async.wait_group %0;" :: "n"(N));
}

__global__ __launch_bounds__(256, 3)
void mc_warp_kernel(const float* __restrict__ pred,
                    const float* __restrict__ mv,
                    const float* __restrict__ wgt,
                    float* __restrict__ out)
{
    __shared__ __align__(16) float tile[2][2][TSZ];   // [stage][r][..] = 45 KB

    const int tid = threadIdx.x;
    const int tx  = tid & 31;
    const int ty  = tid >> 5;
    const int bx  = blockIdx.x, by = blockIdx.y, b = blockIdx.z;
    const int x0blk = bx * 32;
    const int y0blk = by * 32;
    const int x = x0blk + tx;
    const int colbase = x0blk - 16;     // tile cols [colbase, colbase+63]
    const int rowbase = y0blk - PADY;   // tile rows [rowbase, rowbase+44]

    // ---- Precompute taps (4 pixels/thread, 2 r) ----
    // idesc: bit30 = fallback, fast: bit13=dy bit12=dx low12=tile idx
    //                      fallback: bit21=dy bit20=dx low17=global idx
    float w4[4][2][4];
    int   idesc[4][2];
#pragma unroll
    for (int k = 0; k < 4; ++k) {
        const int y = y0blk + ty + 8 * k;
        const int pix = y * Wv + x;
#pragma unroll
        for (int r = 0; r < Rv; ++r) {
            const int nr = b * Rv + r;
            const float mvx = __ldg(mv + (size_t)(nr * 2) * HW + pix) * 0.25f;
            const float mvy = __ldg(mv + (size_t)(nr * 2 + 1) * HW + pix) * 0.25f;
            const float w   = __ldg(wgt + (size_t)nr * HW + pix);

            const float gx = (float)x + mvx;
            const float gy = (float)y + mvy;
            const float x0f = floorf(gx), y0f = floorf(gy);
            const float wx1 = gx - x0f, wx0 = 1.0f - wx1;
            const float wy1 = gy - y0f, wy0 = 1.0f - wy1;

            const int x0 = (int)x0f, y0 = (int)y0f;
            const int x1 = x0 + 1,   y1 = y0 + 1;

            const float vx0 = ((unsigned)x0 < (unsigned)Wv) ? 1.0f : 0.0f;
            const float vx1 = ((unsigned)x1 < (unsigned)Wv) ? 1.0f : 0.0f;
            const float vy0 = ((unsigned)y0 < (unsigned)Hv) ? 1.0f : 0.0f;
            const float vy1 = ((unsigned)y1 < (unsigned)Hv) ? 1.0f : 0.0f;

            const int cx0 = min(max(x0, 0), Wv - 1);
            const int cx1 = min(max(x1, 0), Wv - 1);   // independently clamped
            const int cy0 = min(max(y0, 0), Hv - 1);
            const int cy1 = min(max(y1, 0), Hv - 1);
            const int dx  = cx1 - cx0;                 // 0 or 1
            const int dy  = cy1 - cy0;                 // 0 or 1

            w4[k][r][0] = wy0 * wx0 * vy0 * vx0 * w;
            w4[k][r][1] = wy0 * wx1 * vy0 * vx1 * w;
            w4[k][r][2] = wy1 * wx0 * vy1 * vx0 * w;
            w4[k][r][3] = wy1 * wx1 * vy1 * vx1 * w;

            const int tT = cy0 - rowbase;
            const int tB = cy1 - rowbase;
            const int tX = cx0 - colbase;
            if ((unsigned)tT < TROWS && (unsigned)tB < TROWS &&
                (unsigned)tX <= (TCOLS - 2)) {
                idesc[k][r] = (dy << 13) | (dx << 12) | (tT * TCOLS + tX);
            } else {
                idesc[k][r] = 0x40000000 | (dy << 21) | (dx << 20)
                            | (cy0 * Wv + cx0);
            }
        }
    }

    const float* pb0 = pred + (size_t)(b * Rv + 0) * Cv * HW;
    const float* pb1 = pred + (size_t)(b * Rv + 1) * Cv * HW;
    const bool edge = (bx == 0) || (bx == (Wv / 32 - 1));
    const int cb4 = colbase >> 2;

    float* ob = out + (size_t)b * Cv * HW + (size_t)(y0blk + ty) * Wv + x;

    // ---- tile load (cp.async) for channel c into stage st ----
    auto load_stage = [&](int c, int st) {
        if (!edge) {
            const float4* s0 = (const float4*)(pb0 + (size_t)c * HW);
            const float4* s1 = (const float4*)(pb1 + (size_t)c * HW);
            for (int i = tid; i < TSZ4; i += 256) {
                const int row = i >> 4;           // 16 float4 per tile row
                const int c4  = i & 15;
                const int gcy = min(max(rowbase + row, 0), Hv - 1);
                const int gi  = gcy * (Wv / 4) + cb4 + c4;
                cp_async16((uint32_t)__cvta_generic_to_shared(&tile[st][0][i * 4]), s0 + gi);
                cp_async16((uint32_t)__cvta_generic_to_shared(&tile[st][1][i * 4]), s1 + gi);
            }
        } else {
            const float* s0 = pb0 + (size_t)c * HW;
            const float* s1 = pb1 + (size_t)c * HW;
            for (int i = tid; i < TSZ; i += 256) {
                const int row = i >> 6;
                const int col = i & 63;
                const int gcy = min(max(rowbase + row, 0), Hv - 1);
                const int gcx = min(max(colbase + col, 0), Wv - 1);
                const int gi  = gcy * Wv + gcx;
                cp_async4((uint32_t)__cvta_generic_to_shared(&tile[st][0][i]), s0 + gi);
                cp_async4((uint32_t)__cvta_generic_to_shared(&tile[st][1][i]), s1 + gi);
            }
        }
    };

    load_stage(0, 0);
    cp_commit();

    for (int c = 0; c < Cv; ++c) {
        const int st = c & 1;
        if (c + 1 < Cv) {
            load_stage(c + 1, st ^ 1);
            cp_commit();
            cp_wait<1>();     // stage st complete, stage st^1 may be in flight
        } else {
            cp_wait<0>();
        }
        __syncthreads();

        float* oc = ob + (size_t)c * HW;
#pragma unroll
        for (int k = 0; k < 4; ++k) {
            float s = 0.0f;
#pragma unroll
            for (int r = 0; r < Rv; ++r) {
                const int d = idesc[k][r];
                float t0v, t1v, b0v, b1v;
                if (d < 0x40000000) {
                    const int iT = d & 0xFFF;
                    const int dxv = (d >> 12) & 1;
                    const int iB = iT + ((d >> 13) & 1) * TCOLS;
                    const float* tb = tile[st][r];
                    t0v = tb[iT];
                    t1v = tb[iT + dxv];
                    b0v = tb[iB];
                    b1v = tb[iB + dxv];
                } else {
                    const int gT = d & 0x1FFFF;
                    const int dxv = (d >> 20) & 1;
                    const int gB = gT + ((d >> 21) & 1) * Wv;
                    const float* pc = (r ? pb1 : pb0) + (size_t)c * HW;
                    t0v = __ldg(pc + gT);
                    t1v = __ldg(pc + gT + dxv);
                    b0v = __ldg(pc + gB);
                    b1v = __ldg(pc + gB + dxv);
                }
                s = fmaf(w4[k][r][0], t0v,
                    fmaf(w4[k][r][1], t1v,
                    fmaf(w4[k][r][2], b0v,
                    fmaf(w4[k][r][3], b1v, s))));
            }
            oc[(size_t)(8 * k) * Wv] = s;
        }
        __syncthreads();   // stage st fully consumed before next prefetch overwrites it
    }
}

extern "C" void kernel_launch(void* const* d_in, const int* in_sizes, int n_in,
                              void* d_out, int out_size)
{
    const float* pred = (const float*)d_in[0];
    const float* mv   = (const float*)d_in[1];
    const float* wgt  = (const float*)d_in[2];
    float* out        = (float*)d_out;

    dim3 grid(Wv / 32, Hv / 32, Bv);   // 16 x 8 x 4 = 512 blocks
    mc_warp_kernel<<<grid, 256>>>(pred, mv, wgt, out);
}